// round 9
// baseline (speedup 1.0000x reference)
#include <cuda_runtime.h>
#include <cuda_bf16.h>
#include <math.h>
#include <stdint.h>

#define NB 8
#define T  2048
#define E  1024
#define MT (NB*T)

typedef __nv_bfloat16 bf16;

// ------------------------- scratch (device globals) -------------------------
__device__ bf16 g_Xbh[(size_t)MT*E], g_Xbl[(size_t)MT*E];
__device__ bf16 g_Wqh[(size_t)E*E], g_Wql[(size_t)E*E];
__device__ bf16 g_Wkh[(size_t)E*E], g_Wkl[(size_t)E*E];
__device__ bf16 g_Wvh[(size_t)E*E], g_Wvl[(size_t)E*E];
__device__ bf16 g_Qbh[(size_t)MT*E], g_Qbl[(size_t)MT*E];
__device__ bf16 g_Kbh[(size_t)MT*E], g_Kbl[(size_t)MT*E];
__device__ float g_Vth[(size_t)NB*E*T];          // [b][f][t], tf32-rounded
__device__ float g_S [(size_t)NB*T*T];
__device__ float g_Ph[(size_t)NB*T*T];
__device__ float g_M[NB*T], g_Li[NB*T];

// ------------------------- helpers -------------------------
__device__ __forceinline__ uint32_t smem_u32(const void* p) {
    uint32_t a;
    asm("{ .reg .u64 t; cvta.to.shared.u64 t, %1; cvt.u32.u64 %0, t; }" : "=r"(a) : "l"(p));
    return a;
}
__device__ __forceinline__ float tf32_rna(float x) {
    uint32_t u; asm("cvt.rna.tf32.f32 %0, %1;" : "=r"(u) : "f"(x));
    return __uint_as_float(u);
}
__device__ __forceinline__ void cpa16(uint32_t dst, const void* src) {
    asm volatile("cp.async.cg.shared.global [%0], [%1], 16;" :: "r"(dst), "l"(src) : "memory");
}
__device__ __forceinline__ void cpa_commit() { asm volatile("cp.async.commit_group;" ::: "memory"); }
template<int N> __device__ __forceinline__ void cpa_wait() {
    asm volatile("cp.async.wait_group %0;" :: "n"(N) : "memory");
}
// NOTE: non-volatile — register-only op, lets ptxas schedule around latency.
__device__ __forceinline__ void mma16(float* d, uint32_t a0, uint32_t a1, uint32_t a2, uint32_t a3,
                                      uint32_t b0, uint32_t b1) {
    asm("mma.sync.aligned.m16n8k16.row.col.f32.bf16.bf16.f32 "
        "{%0,%1,%2,%3},{%4,%5,%6,%7},{%8,%9},{%0,%1,%2,%3};"
        : "+f"(d[0]), "+f"(d[1]), "+f"(d[2]), "+f"(d[3])
        : "r"(a0), "r"(a1), "r"(a2), "r"(a3), "r"(b0), "r"(b1));
}
__device__ __forceinline__ void mma8(float* d, uint32_t a0, uint32_t a1, uint32_t a2, uint32_t a3,
                                     uint32_t b0, uint32_t b1) {
    asm("mma.sync.aligned.m16n8k8.row.col.f32.tf32.tf32.f32 "
        "{%0,%1,%2,%3},{%4,%5,%6,%7},{%8,%9},{%0,%1,%2,%3};"
        : "+f"(d[0]), "+f"(d[1]), "+f"(d[2]), "+f"(d[3])
        : "r"(a0), "r"(a1), "r"(a2), "r"(a3), "r"(b0), "r"(b1));
}
__device__ __forceinline__ uint32_t pack_bf2(float x, float y) {
    bf16 hx = __float2bfloat16(x), hy = __float2bfloat16(y);
    uint16_t ux = *(uint16_t*)&hx, uy = *(uint16_t*)&hy;
    uint32_t r;
    asm("mov.b32 %0, {%1, %2};" : "=r"(r) : "h"(ux), "h"(uy));
    return r;
}

// ============================================================
// bf16x2 3-pass GEMM: D = sum_k A[m,k]*B[n,k], 256x128x32, 512 thr, 3-stage
// Pass loop hoisted OUTSIDE (mi,ni): same-acc MMAs are 16 instrs apart.
// MODE 0: proj Q/K  (+bias, bf16 hi/lo split row-major store)
// MODE 1: proj V    (+bias, tf32-rounded fp32 TRANSPOSED store -> Vt[b][f][t])
// MODE 2: scores    (triangle grid, fp32 store to S)
// ============================================================
#define BSTAGE_E 24576
#define BSMEM_BYTES (3*BSTAGE_E*2)      // 147456

template<int MODE>
__global__ void __launch_bounds__(512, 1) gemm_bf16(
    const bf16* __restrict__ pAh, const bf16* __restrict__ pAl,
    const bf16* __restrict__ pBh, const bf16* __restrict__ pBl,
    float* __restrict__ outf, bf16* __restrict__ oh, bf16* __restrict__ ol,
    const float* __restrict__ bias)
{
    const int m0 = blockIdx.y * 256, n0 = blockIdx.x * 128;
    if (MODE == 2 && n0 >= m0 + 256) return;

    extern __shared__ bf16 smb[];
    const uint32_t sb = smem_u32(smb);
    const int tid = threadIdx.x;
    const int lane = tid & 31, warp = tid >> 5;
    const int wm = warp >> 2, wn = warp & 3;
    const int g = lane >> 2, c = lane & 3;
    const int b = blockIdx.z;

    const bf16 *Ah_, *Al_, *Bh_, *Bl_;
    if (MODE == 2) {
        Ah_ = pAh + (size_t)(b*T + m0)*E;  Al_ = pAl + (size_t)(b*T + m0)*E;
        Bh_ = pBh + (size_t)(b*T + n0)*E;  Bl_ = pBl + (size_t)(b*T + n0)*E;
    } else {
        Ah_ = pAh + (size_t)m0*E;  Al_ = pAl + (size_t)m0*E;
        Bh_ = pBh + (size_t)n0*E;  Bl_ = pBl + (size_t)n0*E;
    }
    const int nchunks = E/32;

    auto fill = [&](int ck) {
        const int stg = ck % 3;
        const int k0 = ck * 32;
        for (int i = tid; i < 3072; i += 512) {
            const bf16* srcb; int row; uint32_t soff;
            if (i < 1024)      { srcb = Ah_; row = i >> 2;          soff = 0; }
            else if (i < 2048) { srcb = Al_; row = (i-1024) >> 2;   soff = 8192; }
            else if (i < 2560) { srcb = Bh_; row = (i-2048) >> 2;   soff = 16384; }
            else               { srcb = Bl_; row = (i-2560) >> 2;   soff = 20480; }
            const int seg = i & 3;
            const uint32_t wrd = (uint32_t)((seg << 2) ^ (((row >> 1) & 3) << 2));
            uint32_t dst = sb + (uint32_t)(stg*BSTAGE_E + soff + row*32 + wrd*2) * 2u;
            cpa16(dst, srcb + (size_t)row*E + k0 + seg*8);
        }
        cpa_commit();
    };

    float acc[4][4][4];
    #pragma unroll
    for (int mi = 0; mi < 4; mi++)
        #pragma unroll
        for (int ni = 0; ni < 4; ni++)
            #pragma unroll
            for (int q = 0; q < 4; q++) acc[mi][ni][q] = 0.f;

    fill(0);
    fill(1);

    for (int ck = 0; ck < nchunks; ck++) {
        if (ck + 1 < nchunks) cpa_wait<1>(); else cpa_wait<0>();
        __syncthreads();
        if (ck + 2 < nchunks) fill(ck + 2);

        const bf16* S0 = smb + (ck % 3) * BSTAGE_E;
        const uint32_t* SAh = (const uint32_t*)(S0);
        const uint32_t* SAl = (const uint32_t*)(S0 + 8192);
        const uint32_t* SBh = (const uint32_t*)(S0 + 16384);
        const uint32_t* SBl = (const uint32_t*)(S0 + 20480);

        #pragma unroll
        for (int ks = 0; ks < 2; ks++) {
            const int w0 = 8*ks + c, w1 = w0 + 4;
            uint32_t bh[4][2], bl[4][2];
            #pragma unroll
            for (int ni = 0; ni < 4; ni++) {
                const int rn = wn*32 + ni*8 + g;
                const int sw = ((rn >> 1) & 3) << 2;
                bh[ni][0] = SBh[rn*16 + (w0^sw)];  bh[ni][1] = SBh[rn*16 + (w1^sw)];
                bl[ni][0] = SBl[rn*16 + (w0^sw)];  bl[ni][1] = SBl[rn*16 + (w1^sw)];
            }
            uint32_t af[4][4];
            // ---- A-hi frags ----
            #pragma unroll
            for (int mi = 0; mi < 4; mi++) {
                const int r1 = wm*64 + mi*16 + g, r2 = r1 + 8;
                const int sw = ((r1 >> 1) & 3) << 2;
                af[mi][0] = SAh[r1*16 + (w0^sw)]; af[mi][1] = SAh[r2*16 + (w0^sw)];
                af[mi][2] = SAh[r1*16 + (w1^sw)]; af[mi][3] = SAh[r2*16 + (w1^sw)];
            }
            // pass 1: Ah * Bh   (16 independent MMAs)
            #pragma unroll
            for (int mi = 0; mi < 4; mi++)
                #pragma unroll
                for (int ni = 0; ni < 4; ni++)
                    mma16(acc[mi][ni], af[mi][0], af[mi][1], af[mi][2], af[mi][3],
                          bh[ni][0], bh[ni][1]);
            // pass 2: Ah * Bl
            #pragma unroll
            for (int mi = 0; mi < 4; mi++)
                #pragma unroll
                for (int ni = 0; ni < 4; ni++)
                    mma16(acc[mi][ni], af[mi][0], af[mi][1], af[mi][2], af[mi][3],
                          bl[ni][0], bl[ni][1]);
            // ---- reload af with A-lo ----
            #pragma unroll
            for (int mi = 0; mi < 4; mi++) {
                const int r1 = wm*64 + mi*16 + g, r2 = r1 + 8;
                const int sw = ((r1 >> 1) & 3) << 2;
                af[mi][0] = SAl[r1*16 + (w0^sw)]; af[mi][1] = SAl[r2*16 + (w0^sw)];
                af[mi][2] = SAl[r1*16 + (w1^sw)]; af[mi][3] = SAl[r2*16 + (w1^sw)];
            }
            // pass 3: Al * Bh
            #pragma unroll
            for (int mi = 0; mi < 4; mi++)
                #pragma unroll
                for (int ni = 0; ni < 4; ni++)
                    mma16(acc[mi][ni], af[mi][0], af[mi][1], af[mi][2], af[mi][3],
                          bh[ni][0], bh[ni][1]);
        }
    }

    #pragma unroll
    for (int mi = 0; mi < 4; mi++) {
        #pragma unroll
        for (int ni = 0; ni < 4; ni++) {
            const int r1 = m0 + wm*64 + mi*16 + g, r2 = r1 + 8;
            const int col = n0 + wn*32 + ni*8 + 2*c;
            float* a = acc[mi][ni];
            if (MODE == 0) {
                float2 bs = *(const float2*)(bias + col);
                float y0 = a[0] + bs.x, y1 = a[1] + bs.y;
                float y2 = a[2] + bs.x, y3 = a[3] + bs.y;
                float h0 = __bfloat162float(__float2bfloat16(y0));
                float h1 = __bfloat162float(__float2bfloat16(y1));
                float h2 = __bfloat162float(__float2bfloat16(y2));
                float h3 = __bfloat162float(__float2bfloat16(y3));
                *(uint32_t*)(oh + (size_t)r1*E + col) = pack_bf2(y0, y1);
                *(uint32_t*)(ol + (size_t)r1*E + col) = pack_bf2(y0 - h0, y1 - h1);
                *(uint32_t*)(oh + (size_t)r2*E + col) = pack_bf2(y2, y3);
                *(uint32_t*)(ol + (size_t)r2*E + col) = pack_bf2(y2 - h2, y3 - h3);
            } else if (MODE == 1) {
                float2 bs = *(const float2*)(bias + col);
                const size_t bo = (size_t)(m0 / T) * E * T;
                const int tl1 = (m0 % T) + wm*64 + mi*16 + g, tl2 = tl1 + 8;
                outf[bo + (size_t)col*T     + tl1] = tf32_rna(a[0] + bs.x);
                outf[bo + (size_t)(col+1)*T + tl1] = tf32_rna(a[1] + bs.y);
                outf[bo + (size_t)col*T     + tl2] = tf32_rna(a[2] + bs.x);
                outf[bo + (size_t)(col+1)*T + tl2] = tf32_rna(a[3] + bs.y);
            } else {
                float* Sb = outf + (size_t)b*T*T;
                *(float2*)(Sb + (size_t)r1*T + col) = make_float2(a[0], a[1]);
                *(float2*)(Sb + (size_t)r2*T + col) = make_float2(a[2], a[3]);
            }
        }
    }
}

// ============================================================
// out GEMM: O = P @ Vt^T, tf32 1-pass, 256x128x32, 2-stage
// ============================================================
#define STAGE_F 24576
#define SMEM_BYTES (2*STAGE_F*4)

__global__ void __launch_bounds__(512, 1) gemm_out(
    const float* __restrict__ pA, const float* __restrict__ pB,
    float* __restrict__ out0)
{
    const int m0 = blockIdx.y * 256, n0 = blockIdx.x * 128;
    extern __shared__ float smf[];
    const uint32_t sb = smem_u32(smf);
    const int tid = threadIdx.x;
    const int lane = tid & 31, warp = tid >> 5;
    const int wm = warp >> 2, wn = warp & 3;
    const int g = lane >> 2, c = lane & 3;
    const int b = blockIdx.z;

    const int nchunks = m0/32 + 8;
    const float* A_ = pA + (size_t)b*T*T + (size_t)m0*T;
    const float* B_ = pB + ((size_t)b*E + n0)*T;

    auto fill = [&](int ck) {
        const int stg = ck & 1;
        const int k0 = ck * 32;
        for (int i = tid; i < 3072; i += 512) {
            const float* srcb; int row; uint32_t soff;
            if (i < 2048) { srcb = A_; row = i >> 3;        soff = 0; }
            else          { srcb = B_; row = (i-2048) >> 3; soff = 16384; }
            int k4 = i & 7;
            uint32_t dst = sb + (uint32_t)(stg*STAGE_F + soff + row*32 + ((k4 ^ (row & 7)) << 2)) * 4u;
            cpa16(dst, srcb + (size_t)row*T + k0 + k4*4);
        }
        cpa_commit();
    };

    float acc[4][4][4];
    #pragma unroll
    for (int mi = 0; mi < 4; mi++)
        #pragma unroll
        for (int ni = 0; ni < 4; ni++)
            #pragma unroll
            for (int q = 0; q < 4; q++) acc[mi][ni][q] = 0.f;

    fill(0);

    for (int ck = 0; ck < nchunks; ck++) {
        if (ck + 1 < nchunks) { fill(ck + 1); cpa_wait<1>(); }
        else                  { cpa_wait<0>(); }
        __syncthreads();

        const float* S0 = smf + (ck & 1) * STAGE_F;
        const uint32_t* Sa = (const uint32_t*)(S0);
        const uint32_t* Sv = (const uint32_t*)(S0 + 16384);

        #pragma unroll
        for (int ks = 0; ks < 4; ks++) {
            const int p0 = ((2*ks)     ^ g)*4 + c;
            const int p1 = ((2*ks + 1) ^ g)*4 + c;
            uint32_t bh[4][2];
            #pragma unroll
            for (int ni = 0; ni < 4; ni++) {
                int rn = (wn*32 + ni*8 + g) * 32;
                bh[ni][0] = Sv[rn + p0];  bh[ni][1] = Sv[rn + p1];
            }
            #pragma unroll
            for (int mi = 0; mi < 4; mi++) {
                int r0 = (wm*64 + mi*16 + g) * 32;
                uint32_t a0 = Sa[r0 + p0], a1 = Sa[r0 + 256 + p0];
                uint32_t a2 = Sa[r0 + p1], a3 = Sa[r0 + 256 + p1];
                #pragma unroll
                for (int ni = 0; ni < 4; ni++)
                    mma8(acc[mi][ni], a0, a1, a2, a3, bh[ni][0], bh[ni][1]);
            }
        }
        __syncthreads();
    }

    #pragma unroll
    for (int mi = 0; mi < 4; mi++) {
        #pragma unroll
        for (int ni = 0; ni < 4; ni++) {
            const int r1 = m0 + wm*64 + mi*16 + g, r2 = r1 + 8;
            const int col = n0 + wn*32 + ni*8 + 2*c;
            float* a = acc[mi][ni];
            float* Ob = out0 + (size_t)b*T*E;
            *(float2*)(Ob + (size_t)r1*E + col) = make_float2(a[0], a[1]);
            *(float2*)(Ob + (size_t)r2*E + col) = make_float2(a[2], a[3]);
        }
    }
}

// ------------------------- elementwise kernels -------------------------
__global__ void __launch_bounds__(256) splitk_bf(
    const float* __restrict__ src, bf16* __restrict__ dh, bf16* __restrict__ dl, int n4)
{
    int i = blockIdx.x * 256 + threadIdx.x;
    if (i >= n4) return;
    float4 v = ((const float4*)src)[i];
    uint32_t h0 = pack_bf2(v.x, v.y), h1 = pack_bf2(v.z, v.w);
    float r0 = v.x - __bfloat162float(__float2bfloat16(v.x));
    float r1 = v.y - __bfloat162float(__float2bfloat16(v.y));
    float r2 = v.z - __bfloat162float(__float2bfloat16(v.z));
    float r3 = v.w - __bfloat162float(__float2bfloat16(v.w));
    uint32_t l0 = pack_bf2(r0, r1), l1 = pack_bf2(r2, r3);
    ((uint2*)dh)[i] = make_uint2(h0, h1);
    ((uint2*)dl)[i] = make_uint2(l0, l1);
}

__global__ void __launch_bounds__(256) colstats()
{
    const int bb = blockIdx.y;
    const int j0 = blockIdx.x * 32;
    const int c = threadIdx.x & 31, r = threadIdx.x >> 5;
    const int j = j0 + c;
    const float* S = g_S + (size_t)bb*T*T;
    float m = -INFINITY, l = 0.f;
    for (int i = j0 + r; i < T; i += 8) {
        float v = S[(size_t)i*T + j];
        if (i >= j) {
            if (v <= m) l += __expf(v - m);
            else { l = l * __expf(m - v) + 1.f; m = v; }
        }
    }
    __shared__ float sm_[8][33], sl_[8][33];
    sm_[r][c] = m; sl_[r][c] = l;
    __syncthreads();
    if (r == 0) {
        float M = m, L = l;
        #pragma unroll
        for (int rr = 1; rr < 8; rr++) {
            float m2 = sm_[rr][c], l2 = sl_[rr][c];
            if (m2 > M) { L = L * __expf(M - m2) + l2; M = m2; }
            else if (l2 > 0.f) L += l2 * __expf(m2 - M);
        }
        g_M [bb*T + j] = M;
        g_Li[bb*T + j] = 1.f / L;
    }
}

__global__ void __launch_bounds__(256) psplit()
{
    const int jt = blockIdx.x, it = blockIdx.y;
    const int bb = blockIdx.z;
    const size_t base = (size_t)bb*T*T;
    const int i0 = it*128, j0 = jt*128;
    if (jt > it) {
        if (jt == it + 1 && (it & 1) == 0) {
            for (int idx = threadIdx.x; idx < 128*32; idx += 256) {
                int rr = idx >> 5, c4 = idx & 31;
                *(float4*)(g_Ph + base + (size_t)(i0+rr)*T + j0 + c4*4) =
                    make_float4(0.f, 0.f, 0.f, 0.f);
            }
        }
        return;
    }
    for (int idx = threadIdx.x; idx < 128*32; idx += 256) {
        int rr = idx >> 5, c4 = idx & 31;
        int i = i0 + rr, j = j0 + c4*4;
        float4 s = *(const float4*)(g_S + base + (size_t)i*T + j);
        float sv[4] = {s.x, s.y, s.z, s.w};
        float h[4];
        #pragma unroll
        for (int q = 0; q < 4; q++) {
            int jj = j + q;
            float p = (jj <= i) ? __expf(sv[q] - g_M[bb*T + jj]) * g_Li[bb*T + jj] : 0.f;
            h[q] = tf32_rna(p);
        }
        *(float4*)(g_Ph + base + (size_t)i*T + j) = make_float4(h[0], h[1], h[2], h[3]);
    }
}

// ------------------------- host -------------------------
extern "C" void kernel_launch(void* const* d_in, const int* in_sizes, int n_in,
                              void* d_out, int out_size)
{
    const float* x_emb = (const float*)d_in[0];
    const float* Wk = (const float*)d_in[2];
    const float* bk = (const float*)d_in[3];
    const float* Wq = (const float*)d_in[4];
    const float* bq = (const float*)d_in[5];
    const float* Wv = (const float*)d_in[6];
    const float* bv = (const float*)d_in[7];
    float* out = (float*)d_out;

    void *Xbh,*Xbl,*Wqh,*Wql,*Wkh,*Wkl,*Wvh,*Wvl,*Qbh,*Qbl,*Kbh,*Kbl,*Vth,*Sp,*Ph;
    cudaGetSymbolAddress(&Xbh, g_Xbh); cudaGetSymbolAddress(&Xbl, g_Xbl);
    cudaGetSymbolAddress(&Wqh, g_Wqh); cudaGetSymbolAddress(&Wql, g_Wql);
    cudaGetSymbolAddress(&Wkh, g_Wkh); cudaGetSymbolAddress(&Wkl, g_Wkl);
    cudaGetSymbolAddress(&Wvh, g_Wvh); cudaGetSymbolAddress(&Wvl, g_Wvl);
    cudaGetSymbolAddress(&Qbh, g_Qbh); cudaGetSymbolAddress(&Qbl, g_Qbl);
    cudaGetSymbolAddress(&Kbh, g_Kbh); cudaGetSymbolAddress(&Kbl, g_Kbl);
    cudaGetSymbolAddress(&Vth, g_Vth);
    cudaGetSymbolAddress(&Sp, g_S);    cudaGetSymbolAddress(&Ph, g_Ph);

    cudaFuncSetAttribute(gemm_bf16<0>, cudaFuncAttributeMaxDynamicSharedMemorySize, BSMEM_BYTES);
    cudaFuncSetAttribute(gemm_bf16<1>, cudaFuncAttributeMaxDynamicSharedMemorySize, BSMEM_BYTES);
    cudaFuncSetAttribute(gemm_bf16<2>, cudaFuncAttributeMaxDynamicSharedMemorySize, BSMEM_BYTES);
    cudaFuncSetAttribute(gemm_out,     cudaFuncAttributeMaxDynamicSharedMemorySize, SMEM_BYTES);

    splitk_bf<<<(MT*E/4 + 255)/256, 256>>>(x_emb, (bf16*)Xbh, (bf16*)Xbl, MT*E/4);
    splitk_bf<<<(E*E/4 + 255)/256, 256>>>(Wq, (bf16*)Wqh, (bf16*)Wql, E*E/4);
    splitk_bf<<<(E*E/4 + 255)/256, 256>>>(Wk, (bf16*)Wkh, (bf16*)Wkl, E*E/4);
    splitk_bf<<<(E*E/4 + 255)/256, 256>>>(Wv, (bf16*)Wvh, (bf16*)Wvl, E*E/4);

    dim3 gp(E/128, MT/256);
    gemm_bf16<0><<<gp, 512, BSMEM_BYTES>>>((bf16*)Xbh, (bf16*)Xbl, (bf16*)Wqh, (bf16*)Wql,
                                           nullptr, (bf16*)Qbh, (bf16*)Qbl, bq);
    gemm_bf16<0><<<gp, 512, BSMEM_BYTES>>>((bf16*)Xbh, (bf16*)Xbl, (bf16*)Wkh, (bf16*)Wkl,
                                           nullptr, (bf16*)Kbh, (bf16*)Kbl, bk);
    gemm_bf16<1><<<gp, 512, BSMEM_BYTES>>>((bf16*)Xbh, (bf16*)Xbl, (bf16*)Wvh, (bf16*)Wvl,
                                           (float*)Vth, nullptr, nullptr, bv);

    dim3 gs(T/128, T/256, NB);
    gemm_bf16<2><<<gs, 512, BSMEM_BYTES>>>((bf16*)Qbh, (bf16*)Qbl, (bf16*)Kbh, (bf16*)Kbl,
                                           (float*)Sp, nullptr, nullptr, nullptr);

    dim3 gc(T/32, NB);
    colstats<<<gc, 256>>>();
    psplit<<<dim3(T/128, T/128, NB), 256>>>();

    dim3 go(E/128, T/256, NB);
    gemm_out<<<go, 512, SMEM_BYTES>>>((float*)Ph, (float*)Vth, out);
}

// round 10
// speedup vs baseline: 1.2328x; 1.2328x over previous
#include <cuda_runtime.h>
#include <cuda.h>
#include <cuda_bf16.h>
#include <math.h>
#include <stdint.h>

#define NB 8
#define T  2048
#define E  1024
#define MT (NB*T)

typedef __nv_bfloat16 bf16;

// ------------------------- scratch (device globals) -------------------------
__device__ bf16 g_Xbh[(size_t)MT*E], g_Xbl[(size_t)MT*E];
__device__ bf16 g_Wqh[(size_t)E*E], g_Wql[(size_t)E*E];
__device__ bf16 g_Wkh[(size_t)E*E], g_Wkl[(size_t)E*E];
__device__ bf16 g_Wvh[(size_t)E*E], g_Wvl[(size_t)E*E];
__device__ bf16 g_Qbh[(size_t)MT*E], g_Qbl[(size_t)MT*E];
__device__ bf16 g_Kbh[(size_t)MT*E], g_Kbl[(size_t)MT*E];
__device__ float g_Vth[(size_t)NB*E*T];          // [b][f][t], tf32-rounded
__device__ float g_S [(size_t)NB*T*T];
__device__ float g_Ph[(size_t)NB*T*T];
__device__ float g_M[NB*T], g_Li[NB*T];

// ------------------------- helpers -------------------------
__device__ __forceinline__ uint32_t smem_u32(const void* p) {
    uint32_t a;
    asm("{ .reg .u64 t; cvta.to.shared.u64 t, %1; cvt.u32.u64 %0, t; }" : "=r"(a) : "l"(p));
    return a;
}
__device__ __forceinline__ float tf32_rna(float x) {
    uint32_t u; asm("cvt.rna.tf32.f32 %0, %1;" : "=r"(u) : "f"(x));
    return __uint_as_float(u);
}
__device__ __forceinline__ void tma2d(uint32_t dst, const void* map, int x, int y, uint32_t mbar) {
    asm volatile("cp.async.bulk.tensor.2d.shared::cta.global.tile.mbarrier::complete_tx::bytes "
                 "[%0], [%1, {%2, %3}], [%4];"
                 :: "r"(dst), "l"(map), "r"(x), "r"(y), "r"(mbar) : "memory");
}
#define MBAR_INIT(a, c) \
    asm volatile("mbarrier.init.shared.b64 [%0], %1;" :: "r"((uint32_t)(a)), "r"((uint32_t)(c)) : "memory")
#define MBAR_EXPECT(a, b) \
    asm volatile("mbarrier.arrive.expect_tx.shared.b64 _, [%0], %1;" :: "r"((uint32_t)(a)), "r"((uint32_t)(b)) : "memory")
#define MBAR_WAIT(a, ph) do { \
    uint32_t _m = (uint32_t)(a), _p = (uint32_t)(ph), _d; \
    asm volatile("{\n\t.reg .pred p;\n\t" \
        "mbarrier.try_wait.parity.acquire.cta.shared::cta.b64 p, [%1], %2;\n\t" \
        "selp.b32 %0,1,0,p;\n\t}" : "=r"(_d) : "r"(_m), "r"(_p) : "memory"); \
    if (!_d) { \
        asm volatile("{\n\t.reg .pred P1;\n\t" \
            "WL_%=:\n\t" \
            "mbarrier.try_wait.parity.acquire.cta.shared::cta.b64 P1, [%0], %1, 0x989680;\n\t" \
            "@P1 bra.uni WD_%=;\n\tbra.uni WL_%=;\n\tWD_%=:\n\t}" \
            :: "r"(_m), "r"(_p) : "memory"); \
    } \
} while(0)
__device__ __forceinline__ void mma16(float* d, uint32_t a0, uint32_t a1, uint32_t a2, uint32_t a3,
                                      uint32_t b0, uint32_t b1) {
    asm("mma.sync.aligned.m16n8k16.row.col.f32.bf16.bf16.f32 "
        "{%0,%1,%2,%3},{%4,%5,%6,%7},{%8,%9},{%0,%1,%2,%3};"
        : "+f"(d[0]), "+f"(d[1]), "+f"(d[2]), "+f"(d[3])
        : "r"(a0), "r"(a1), "r"(a2), "r"(a3), "r"(b0), "r"(b1));
}
__device__ __forceinline__ void mma8(float* d, uint32_t a0, uint32_t a1, uint32_t a2, uint32_t a3,
                                     uint32_t b0, uint32_t b1) {
    asm("mma.sync.aligned.m16n8k8.row.col.f32.tf32.tf32.f32 "
        "{%0,%1,%2,%3},{%4,%5,%6,%7},{%8,%9},{%0,%1,%2,%3};"
        : "+f"(d[0]), "+f"(d[1]), "+f"(d[2]), "+f"(d[3])
        : "r"(a0), "r"(a1), "r"(a2), "r"(a3), "r"(b0), "r"(b1));
}
__device__ __forceinline__ uint32_t pack_bf2(float x, float y) {
    bf16 hx = __float2bfloat16(x), hy = __float2bfloat16(y);
    uint16_t ux = *(uint16_t*)&hx, uy = *(uint16_t*)&hy;
    uint32_t r;
    asm("mov.b32 %0, {%1, %2};" : "=r"(r) : "h"(ux), "h"(uy));
    return r;
}

// ============================================================
// bf16x2 3-pass GEMM with TMA loads.
// D = sum_k A[m,k]*B[n,k] (NT). Tile 256x128, BK=64, 512 thr, 2-stage.
// SMEM: per stage  Ah(32K) Al(32K) Bh(16K) Bl(16K) = 96KB, TMA SW128.
// MODE 0: proj Q/K  (+bias, bf16 hi/lo split row-major store)
// MODE 1: proj V    (+bias, tf32-rounded fp32 TRANSPOSED store -> Vt)
// MODE 2: scores    (triangle grid, fp32 store to S)
// ============================================================
#define BSTG 98304
#define BSMEM_BYTES (2*BSTG)

template<int MODE>
__global__ void __launch_bounds__(512, 1) gemm_bf16(
    const __grid_constant__ CUtensorMap mAh, const __grid_constant__ CUtensorMap mAl,
    const __grid_constant__ CUtensorMap mBh, const __grid_constant__ CUtensorMap mBl,
    float* __restrict__ outf, bf16* __restrict__ oh, bf16* __restrict__ ol,
    const float* __restrict__ bias)
{
    const int m0 = blockIdx.y * 256, n0 = blockIdx.x * 128;
    if (MODE == 2 && n0 >= m0 + 256) return;

    extern __shared__ __align__(1024) char smem[];
    __shared__ __align__(8) uint64_t mbar[2];
    const uint32_t sb = smem_u32(smem);
    const uint32_t mb0 = smem_u32(&mbar[0]), mb1 = smem_u32(&mbar[1]);
    const int tid = threadIdx.x;
    const int lane = tid & 31, warp = tid >> 5;
    const int wm = warp >> 2, wn = warp & 3;
    const int g = lane >> 2, c = lane & 3;
    const int b = blockIdx.z;

    const int rowA = (MODE == 2) ? b*T + m0 : m0;
    const int rowB = (MODE == 2) ? b*T + n0 : n0;
    const int nch = E/64;  // 16

    if (tid == 0) { MBAR_INIT(mb0, 1); MBAR_INIT(mb1, 1); }
    __syncthreads();

    auto issue = [&](int ck) {
        uint32_t st = ck & 1;
        uint32_t base = sb + st*BSTG;
        uint32_t mb = st ? mb1 : mb0;
        MBAR_EXPECT(mb, BSTG);
        tma2d(base + 0,     &mAh, 64*ck, rowA, mb);
        tma2d(base + 32768, &mAl, 64*ck, rowA, mb);
        tma2d(base + 65536, &mBh, 64*ck, rowB, mb);
        tma2d(base + 81920, &mBl, 64*ck, rowB, mb);
    };
    if (tid == 0) { issue(0); issue(1); }

    float acc[4][4][4];
    #pragma unroll
    for (int mi = 0; mi < 4; mi++)
        #pragma unroll
        for (int ni = 0; ni < 4; ni++)
            #pragma unroll
            for (int q = 0; q < 4; q++) acc[mi][ni][q] = 0.f;

    const int sw = g << 2;

    for (int ck = 0; ck < nch; ck++) {
        MBAR_WAIT((ck & 1) ? mb1 : mb0, (ck >> 1) & 1);

        const uint32_t* Wb = (const uint32_t*)(smem + (ck & 1)*BSTG);
        const uint32_t* SAh = Wb;
        const uint32_t* SAl = Wb + 8192;
        const uint32_t* SBh = Wb + 16384;
        const uint32_t* SBl = Wb + 20480;

        #pragma unroll
        for (int ks = 0; ks < 4; ks++) {
            const int u0 = (8*ks + c) ^ sw;
            const int u1 = (8*ks + c + 4) ^ sw;
            uint32_t bh[4][2], bl[4][2];
            #pragma unroll
            for (int ni = 0; ni < 4; ni++) {
                const int rn = (wn*32 + ni*8 + g) * 32;
                bh[ni][0] = SBh[rn + u0];  bh[ni][1] = SBh[rn + u1];
                bl[ni][0] = SBl[rn + u0];  bl[ni][1] = SBl[rn + u1];
            }
            uint32_t af[4][4];
            #pragma unroll
            for (int mi = 0; mi < 4; mi++) {
                const int r1 = (wm*64 + mi*16 + g) * 32, r2 = r1 + 8*32;
                af[mi][0] = SAh[r1 + u0]; af[mi][1] = SAh[r2 + u0];
                af[mi][2] = SAh[r1 + u1]; af[mi][3] = SAh[r2 + u1];
            }
            #pragma unroll
            for (int mi = 0; mi < 4; mi++)
                #pragma unroll
                for (int ni = 0; ni < 4; ni++)
                    mma16(acc[mi][ni], af[mi][0], af[mi][1], af[mi][2], af[mi][3],
                          bh[ni][0], bh[ni][1]);
            #pragma unroll
            for (int mi = 0; mi < 4; mi++)
                #pragma unroll
                for (int ni = 0; ni < 4; ni++)
                    mma16(acc[mi][ni], af[mi][0], af[mi][1], af[mi][2], af[mi][3],
                          bl[ni][0], bl[ni][1]);
            #pragma unroll
            for (int mi = 0; mi < 4; mi++) {
                const int r1 = (wm*64 + mi*16 + g) * 32, r2 = r1 + 8*32;
                af[mi][0] = SAl[r1 + u0]; af[mi][1] = SAl[r2 + u0];
                af[mi][2] = SAl[r1 + u1]; af[mi][3] = SAl[r2 + u1];
            }
            #pragma unroll
            for (int mi = 0; mi < 4; mi++)
                #pragma unroll
                for (int ni = 0; ni < 4; ni++)
                    mma16(acc[mi][ni], af[mi][0], af[mi][1], af[mi][2], af[mi][3],
                          bh[ni][0], bh[ni][1]);
        }
        __syncthreads();
        if (tid == 0 && ck + 2 < nch) issue(ck + 2);
    }

    #pragma unroll
    for (int mi = 0; mi < 4; mi++) {
        #pragma unroll
        for (int ni = 0; ni < 4; ni++) {
            const int r1 = m0 + wm*64 + mi*16 + g, r2 = r1 + 8;
            const int col = n0 + wn*32 + ni*8 + 2*c;
            float* a = acc[mi][ni];
            if (MODE == 0) {
                float2 bs = *(const float2*)(bias + col);
                float y0 = a[0] + bs.x, y1 = a[1] + bs.y;
                float y2 = a[2] + bs.x, y3 = a[3] + bs.y;
                float h0 = __bfloat162float(__float2bfloat16(y0));
                float h1 = __bfloat162float(__float2bfloat16(y1));
                float h2 = __bfloat162float(__float2bfloat16(y2));
                float h3 = __bfloat162float(__float2bfloat16(y3));
                *(uint32_t*)(oh + (size_t)r1*E + col) = pack_bf2(y0, y1);
                *(uint32_t*)(ol + (size_t)r1*E + col) = pack_bf2(y0 - h0, y1 - h1);
                *(uint32_t*)(oh + (size_t)r2*E + col) = pack_bf2(y2, y3);
                *(uint32_t*)(ol + (size_t)r2*E + col) = pack_bf2(y2 - h2, y3 - h3);
            } else if (MODE == 1) {
                float2 bs = *(const float2*)(bias + col);
                const size_t bo = (size_t)(m0 / T) * E * T;
                const int tl1 = (m0 % T) + wm*64 + mi*16 + g, tl2 = tl1 + 8;
                outf[bo + (size_t)col*T     + tl1] = tf32_rna(a[0] + bs.x);
                outf[bo + (size_t)(col+1)*T + tl1] = tf32_rna(a[1] + bs.y);
                outf[bo + (size_t)col*T     + tl2] = tf32_rna(a[2] + bs.x);
                outf[bo + (size_t)(col+1)*T + tl2] = tf32_rna(a[3] + bs.y);
            } else {
                float* Sb = outf + (size_t)b*T*T;
                *(float2*)(Sb + (size_t)r1*T + col) = make_float2(a[0], a[1]);
                *(float2*)(Sb + (size_t)r2*T + col) = make_float2(a[2], a[3]);
            }
        }
    }
}

// ============================================================
// out GEMM with TMA: O = P @ Vt^T, tf32 1-pass, 256x128, BK=32, 2-stage
// SMEM per stage: A(32K) B(16K) = 48KB, fp32 rows = 128B, SW128.
// ============================================================
#define OSTG 49152
#define OSMEM_BYTES (2*OSTG)

__global__ void __launch_bounds__(512, 1) gemm_out(
    const __grid_constant__ CUtensorMap mA, const __grid_constant__ CUtensorMap mB,
    float* __restrict__ out0)
{
    const int m0 = blockIdx.y * 256, n0 = blockIdx.x * 128;
    extern __shared__ __align__(1024) char smem[];
    __shared__ __align__(8) uint64_t mbar[2];
    const uint32_t sb = smem_u32(smem);
    const uint32_t mb0 = smem_u32(&mbar[0]), mb1 = smem_u32(&mbar[1]);
    const int tid = threadIdx.x;
    const int lane = tid & 31, warp = tid >> 5;
    const int wm = warp >> 2, wn = warp & 3;
    const int g = lane >> 2, c = lane & 3;
    const int b = blockIdx.z;

    const int rowA = b*T + m0;
    const int rowB = b*E + n0;
    const int nch = m0/32 + 8;

    if (tid == 0) { MBAR_INIT(mb0, 1); MBAR_INIT(mb1, 1); }
    __syncthreads();

    auto issue = [&](int ck) {
        uint32_t st = ck & 1;
        uint32_t base = sb + st*OSTG;
        uint32_t mb = st ? mb1 : mb0;
        MBAR_EXPECT(mb, OSTG);
        tma2d(base + 0,     &mA, 32*ck, rowA, mb);
        tma2d(base + 32768, &mB, 32*ck, rowB, mb);
    };
    if (tid == 0) { issue(0); issue(1); }

    float acc[4][4][4];
    #pragma unroll
    for (int mi = 0; mi < 4; mi++)
        #pragma unroll
        for (int ni = 0; ni < 4; ni++)
            #pragma unroll
            for (int q = 0; q < 4; q++) acc[mi][ni][q] = 0.f;

    const int sw = g << 2;

    for (int ck = 0; ck < nch; ck++) {
        MBAR_WAIT((ck & 1) ? mb1 : mb0, (ck >> 1) & 1);

        const uint32_t* Wb = (const uint32_t*)(smem + (ck & 1)*OSTG);
        const uint32_t* Sa = Wb;
        const uint32_t* Sv = Wb + 8192;

        #pragma unroll
        for (int ks = 0; ks < 4; ks++) {
            const int u0 = (8*ks + c) ^ sw;
            const int u1 = (8*ks + c + 4) ^ sw;
            uint32_t bh[4][2];
            #pragma unroll
            for (int ni = 0; ni < 4; ni++) {
                const int rn = (wn*32 + ni*8 + g) * 32;
                bh[ni][0] = Sv[rn + u0];  bh[ni][1] = Sv[rn + u1];
            }
            #pragma unroll
            for (int mi = 0; mi < 4; mi++) {
                const int r1 = (wm*64 + mi*16 + g) * 32, r2 = r1 + 8*32;
                uint32_t a0 = Sa[r1 + u0], a1 = Sa[r2 + u0];
                uint32_t a2 = Sa[r1 + u1], a3 = Sa[r2 + u1];
                #pragma unroll
                for (int ni = 0; ni < 4; ni++)
                    mma8(acc[mi][ni], a0, a1, a2, a3, bh[ni][0], bh[ni][1]);
            }
        }
        __syncthreads();
        if (tid == 0 && ck + 2 < nch) issue(ck + 2);
    }

    #pragma unroll
    for (int mi = 0; mi < 4; mi++) {
        #pragma unroll
        for (int ni = 0; ni < 4; ni++) {
            const int r1 = m0 + wm*64 + mi*16 + g, r2 = r1 + 8;
            const int col = n0 + wn*32 + ni*8 + 2*c;
            float* a = acc[mi][ni];
            float* Ob = out0 + (size_t)b*T*E;
            *(float2*)(Ob + (size_t)r1*E + col) = make_float2(a[0], a[1]);
            *(float2*)(Ob + (size_t)r2*E + col) = make_float2(a[2], a[3]);
        }
    }
}

// ------------------------- elementwise kernels -------------------------
__global__ void __launch_bounds__(256) splitk_bf(
    const float* __restrict__ src, bf16* __restrict__ dh, bf16* __restrict__ dl, int n4)
{
    int i = blockIdx.x * 256 + threadIdx.x;
    if (i >= n4) return;
    float4 v = ((const float4*)src)[i];
    uint32_t h0 = pack_bf2(v.x, v.y), h1 = pack_bf2(v.z, v.w);
    float r0 = v.x - __bfloat162float(__float2bfloat16(v.x));
    float r1 = v.y - __bfloat162float(__float2bfloat16(v.y));
    float r2 = v.z - __bfloat162float(__float2bfloat16(v.z));
    float r3 = v.w - __bfloat162float(__float2bfloat16(v.w));
    uint32_t l0 = pack_bf2(r0, r1), l1 = pack_bf2(r2, r3);
    ((uint2*)dh)[i] = make_uint2(h0, h1);
    ((uint2*)dl)[i] = make_uint2(l0, l1);
}

__global__ void __launch_bounds__(256) colstats()
{
    const int bb = blockIdx.y;
    const int j0 = blockIdx.x * 32;
    const int c = threadIdx.x & 31, r = threadIdx.x >> 5;
    const int j = j0 + c;
    const float* S = g_S + (size_t)bb*T*T;
    float m = -INFINITY, l = 0.f;
    for (int i = j0 + r; i < T; i += 8) {
        float v = S[(size_t)i*T + j];
        if (i >= j) {
            if (v <= m) l += __expf(v - m);
            else { l = l * __expf(m - v) + 1.f; m = v; }
        }
    }
    __shared__ float sm_[8][33], sl_[8][33];
    sm_[r][c] = m; sl_[r][c] = l;
    __syncthreads();
    if (r == 0) {
        float M = m, L = l;
        #pragma unroll
        for (int rr = 1; rr < 8; rr++) {
            float m2 = sm_[rr][c], l2 = sl_[rr][c];
            if (m2 > M) { L = L * __expf(M - m2) + l2; M = m2; }
            else if (l2 > 0.f) L += l2 * __expf(m2 - M);
        }
        g_M [bb*T + j] = M;
        g_Li[bb*T + j] = 1.f / L;
    }
}

__global__ void __launch_bounds__(256) psplit()
{
    const int jt = blockIdx.x, it = blockIdx.y;
    const int bb = blockIdx.z;
    const size_t base = (size_t)bb*T*T;
    const int i0 = it*128, j0 = jt*128;
    if (jt > it) {
        if (jt == it + 1 && (it & 1) == 0) {
            for (int idx = threadIdx.x; idx < 128*32; idx += 256) {
                int rr = idx >> 5, c4 = idx & 31;
                *(float4*)(g_Ph + base + (size_t)(i0+rr)*T + j0 + c4*4) =
                    make_float4(0.f, 0.f, 0.f, 0.f);
            }
        }
        return;
    }
    for (int idx = threadIdx.x; idx < 128*32; idx += 256) {
        int rr = idx >> 5, c4 = idx & 31;
        int i = i0 + rr, j = j0 + c4*4;
        float4 s = *(const float4*)(g_S + base + (size_t)i*T + j);
        float sv[4] = {s.x, s.y, s.z, s.w};
        float h[4];
        #pragma unroll
        for (int q = 0; q < 4; q++) {
            int jj = j + q;
            float p = (jj <= i) ? __expf(sv[q] - g_M[bb*T + jj]) * g_Li[bb*T + jj] : 0.f;
            h[q] = tf32_rna(p);
        }
        *(float4*)(g_Ph + base + (size_t)i*T + j) = make_float4(h[0], h[1], h[2], h[3]);
    }
}

// ------------------------- host -------------------------
typedef CUresult (*PFN_encode)(CUtensorMap*, CUtensorMapDataType, cuuint32_t, void*,
    const cuuint64_t*, const cuuint64_t*, const cuuint32_t*, const cuuint32_t*,
    CUtensorMapInterleave, CUtensorMapSwizzle, CUtensorMapL2promotion, CUtensorMapFloatOOBfill);

static void mk2d(PFN_encode enc, CUtensorMap* tm, void* p, CUtensorMapDataType dt,
                 uint64_t w, uint64_t h, uint32_t bw, uint32_t bh, uint32_t esize) {
    cuuint64_t dims[2]    = {w, h};
    cuuint64_t strides[1] = {w * esize};
    cuuint32_t box[2]     = {bw, bh};
    cuuint32_t es[2]      = {1, 1};
    enc(tm, dt, 2, p, dims, strides, box, es,
        CU_TENSOR_MAP_INTERLEAVE_NONE, CU_TENSOR_MAP_SWIZZLE_128B,
        CU_TENSOR_MAP_L2_PROMOTION_L2_128B, CU_TENSOR_MAP_FLOAT_OOB_FILL_NONE);
}

extern "C" void kernel_launch(void* const* d_in, const int* in_sizes, int n_in,
                              void* d_out, int out_size)
{
    const float* x_emb = (const float*)d_in[0];
    const float* Wk = (const float*)d_in[2];
    const float* bk = (const float*)d_in[3];
    const float* Wq = (const float*)d_in[4];
    const float* bq = (const float*)d_in[5];
    const float* Wv = (const float*)d_in[6];
    const float* bv = (const float*)d_in[7];
    float* out = (float*)d_out;

    void* fp = nullptr;
    cudaDriverEntryPointQueryResult qst;
    cudaGetDriverEntryPointByVersion("cuTensorMapEncodeTiled", &fp, 12000, cudaEnableDefault, &qst);
    PFN_encode enc = (PFN_encode)fp;

    void *Xbh,*Xbl,*Wqh,*Wql,*Wkh,*Wkl,*Wvh,*Wvl,*Qbh,*Qbl,*Kbh,*Kbl,*Vth,*Sp,*Ph;
    cudaGetSymbolAddress(&Xbh, g_Xbh); cudaGetSymbolAddress(&Xbl, g_Xbl);
    cudaGetSymbolAddress(&Wqh, g_Wqh); cudaGetSymbolAddress(&Wql, g_Wql);
    cudaGetSymbolAddress(&Wkh, g_Wkh); cudaGetSymbolAddress(&Wkl, g_Wkl);
    cudaGetSymbolAddress(&Wvh, g_Wvh); cudaGetSymbolAddress(&Wvl, g_Wvl);
    cudaGetSymbolAddress(&Qbh, g_Qbh); cudaGetSymbolAddress(&Qbl, g_Qbl);
    cudaGetSymbolAddress(&Kbh, g_Kbh); cudaGetSymbolAddress(&Kbl, g_Kbl);
    cudaGetSymbolAddress(&Vth, g_Vth);
    cudaGetSymbolAddress(&Sp, g_S);    cudaGetSymbolAddress(&Ph, g_Ph);

    const CUtensorMapDataType BF = CU_TENSOR_MAP_DATA_TYPE_BFLOAT16;
    const CUtensorMapDataType F32 = CU_TENSOR_MAP_DATA_TYPE_FLOAT32;
    CUtensorMap tXh, tXl, tWqh, tWql, tWkh, tWkl, tWvh, tWvl;
    CUtensorMap tQh, tQl, tKh, tKl, tP, tV;
    mk2d(enc, &tXh, Xbh, BF, E, MT, 64, 256, 2);
    mk2d(enc, &tXl, Xbl, BF, E, MT, 64, 256, 2);
    mk2d(enc, &tWqh, Wqh, BF, E, E, 64, 128, 2);
    mk2d(enc, &tWql, Wql, BF, E, E, 64, 128, 2);
    mk2d(enc, &tWkh, Wkh, BF, E, E, 64, 128, 2);
    mk2d(enc, &tWkl, Wkl, BF, E, E, 64, 128, 2);
    mk2d(enc, &tWvh, Wvh, BF, E, E, 64, 128, 2);
    mk2d(enc, &tWvl, Wvl, BF, E, E, 64, 128, 2);
    mk2d(enc, &tQh, Qbh, BF, E, MT, 64, 256, 2);
    mk2d(enc, &tQl, Qbl, BF, E, MT, 64, 256, 2);
    mk2d(enc, &tKh, Kbh, BF, E, MT, 64, 128, 2);
    mk2d(enc, &tKl, Kbl, BF, E, MT, 64, 128, 2);
    mk2d(enc, &tP, Ph, F32, T, (uint64_t)NB*T, 32, 256, 4);
    mk2d(enc, &tV, Vth, F32, T, (uint64_t)NB*E, 32, 128, 4);

    cudaFuncSetAttribute(gemm_bf16<0>, cudaFuncAttributeMaxDynamicSharedMemorySize, BSMEM_BYTES);
    cudaFuncSetAttribute(gemm_bf16<1>, cudaFuncAttributeMaxDynamicSharedMemorySize, BSMEM_BYTES);
    cudaFuncSetAttribute(gemm_bf16<2>, cudaFuncAttributeMaxDynamicSharedMemorySize, BSMEM_BYTES);
    cudaFuncSetAttribute(gemm_out,     cudaFuncAttributeMaxDynamicSharedMemorySize, OSMEM_BYTES);

    splitk_bf<<<(MT*E/4 + 255)/256, 256>>>(x_emb, (bf16*)Xbh, (bf16*)Xbl, MT*E/4);
    splitk_bf<<<(E*E/4 + 255)/256, 256>>>(Wq, (bf16*)Wqh, (bf16*)Wql, E*E/4);
    splitk_bf<<<(E*E/4 + 255)/256, 256>>>(Wk, (bf16*)Wkh, (bf16*)Wkl, E*E/4);
    splitk_bf<<<(E*E/4 + 255)/256, 256>>>(Wv, (bf16*)Wvh, (bf16*)Wvl, E*E/4);

    dim3 gp(E/128, MT/256);
    gemm_bf16<0><<<gp, 512, BSMEM_BYTES>>>(tXh, tXl, tWqh, tWql,
                                           nullptr, (bf16*)Qbh, (bf16*)Qbl, bq);
    gemm_bf16<0><<<gp, 512, BSMEM_BYTES>>>(tXh, tXl, tWkh, tWkl,
                                           nullptr, (bf16*)Kbh, (bf16*)Kbl, bk);
    gemm_bf16<1><<<gp, 512, BSMEM_BYTES>>>(tXh, tXl, tWvh, tWvl,
                                           (float*)Vth, nullptr, nullptr, bv);

    dim3 gs(T/128, T/256, NB);
    gemm_bf16<2><<<gs, 512, BSMEM_BYTES>>>(tQh, tQl, tKh, tKl,
                                           (float*)Sp, nullptr, nullptr, nullptr);

    dim3 gc(T/32, NB);
    colstats<<<gc, 256>>>();
    psplit<<<dim3(T/128, T/128, NB), 256>>>();

    dim3 go(E/128, T/256, NB);
    gemm_out<<<go, 512, OSMEM_BYTES>>>(tP, tV, out);
}

// round 11
// speedup vs baseline: 1.3118x; 1.0640x over previous
#include <cuda_runtime.h>
#include <cuda.h>
#include <cuda_bf16.h>
#include <math.h>
#include <stdint.h>

#define NB 8
#define T  2048
#define E  1024
#define MT (NB*T)

typedef __nv_bfloat16 bf16;

// ------------------------- scratch (device globals) -------------------------
__device__ bf16 g_Xbh[(size_t)MT*E], g_Xbl[(size_t)MT*E];
__device__ bf16 g_Wqh[(size_t)E*E], g_Wql[(size_t)E*E];
__device__ bf16 g_Wkh[(size_t)E*E], g_Wkl[(size_t)E*E];
__device__ bf16 g_Wvh[(size_t)E*E], g_Wvl[(size_t)E*E];
__device__ bf16 g_Qbh[(size_t)MT*E], g_Qbl[(size_t)MT*E];
__device__ bf16 g_Kbh[(size_t)MT*E], g_Kbl[(size_t)MT*E];
__device__ float g_Vth[(size_t)NB*E*T];          // [b][f][t], tf32-rounded
__device__ float g_S [(size_t)NB*T*T];
__device__ float g_Ph[(size_t)NB*T*T];
__device__ float g_M[NB*T], g_Li[NB*T];

// ------------------------- helpers -------------------------
__device__ __forceinline__ uint32_t smem_u32(const void* p) {
    uint32_t a;
    asm("{ .reg .u64 t; cvta.to.shared.u64 t, %1; cvt.u32.u64 %0, t; }" : "=r"(a) : "l"(p));
    return a;
}
__device__ __forceinline__ float tf32_rna(float x) {
    uint32_t u; asm("cvt.rna.tf32.f32 %0, %1;" : "=r"(u) : "f"(x));
    return __uint_as_float(u);
}
__device__ __forceinline__ void tma2d(uint32_t dst, const void* map, int x, int y, uint32_t mbar) {
    asm volatile("cp.async.bulk.tensor.2d.shared::cta.global.tile.mbarrier::complete_tx::bytes "
                 "[%0], [%1, {%2, %3}], [%4];"
                 :: "r"(dst), "l"(map), "r"(x), "r"(y), "r"(mbar) : "memory");
}
#define MBAR_INIT(a, c) \
    asm volatile("mbarrier.init.shared.b64 [%0], %1;" :: "r"((uint32_t)(a)), "r"((uint32_t)(c)) : "memory")
#define MBAR_EXPECT(a, b) \
    asm volatile("mbarrier.arrive.expect_tx.shared.b64 _, [%0], %1;" :: "r"((uint32_t)(a)), "r"((uint32_t)(b)) : "memory")
#define MBAR_WAIT(a, ph) do { \
    uint32_t _m = (uint32_t)(a), _p = (uint32_t)(ph), _d; \
    asm volatile("{\n\t.reg .pred p;\n\t" \
        "mbarrier.try_wait.parity.acquire.cta.shared::cta.b64 p, [%1], %2;\n\t" \
        "selp.b32 %0,1,0,p;\n\t}" : "=r"(_d) : "r"(_m), "r"(_p) : "memory"); \
    if (!_d) { \
        asm volatile("{\n\t.reg .pred P1;\n\t" \
            "WL_%=:\n\t" \
            "mbarrier.try_wait.parity.acquire.cta.shared::cta.b64 P1, [%0], %1, 0x989680;\n\t" \
            "@P1 bra.uni WD_%=;\n\tbra.uni WL_%=;\n\tWD_%=:\n\t}" \
            :: "r"(_m), "r"(_p) : "memory"); \
    } \
} while(0)
__device__ __forceinline__ void ldsm4(uint32_t& r0, uint32_t& r1, uint32_t& r2, uint32_t& r3,
                                      uint32_t addr) {
    asm volatile("ldmatrix.sync.aligned.m8n8.x4.shared.b16 {%0,%1,%2,%3}, [%4];"
                 : "=r"(r0), "=r"(r1), "=r"(r2), "=r"(r3) : "r"(addr));
}
__device__ __forceinline__ void mma16(float* d, uint32_t a0, uint32_t a1, uint32_t a2, uint32_t a3,
                                      uint32_t b0, uint32_t b1) {
    asm("mma.sync.aligned.m16n8k16.row.col.f32.bf16.bf16.f32 "
        "{%0,%1,%2,%3},{%4,%5,%6,%7},{%8,%9},{%0,%1,%2,%3};"
        : "+f"(d[0]), "+f"(d[1]), "+f"(d[2]), "+f"(d[3])
        : "r"(a0), "r"(a1), "r"(a2), "r"(a3), "r"(b0), "r"(b1));
}
__device__ __forceinline__ void mma8(float* d, uint32_t a0, uint32_t a1, uint32_t a2, uint32_t a3,
                                     uint32_t b0, uint32_t b1) {
    asm("mma.sync.aligned.m16n8k8.row.col.f32.tf32.tf32.f32 "
        "{%0,%1,%2,%3},{%4,%5,%6,%7},{%8,%9},{%0,%1,%2,%3};"
        : "+f"(d[0]), "+f"(d[1]), "+f"(d[2]), "+f"(d[3])
        : "r"(a0), "r"(a1), "r"(a2), "r"(a3), "r"(b0), "r"(b1));
}
__device__ __forceinline__ uint32_t pack_bf2(float x, float y) {
    bf16 hx = __float2bfloat16(x), hy = __float2bfloat16(y);
    uint16_t ux = *(uint16_t*)&hx, uy = *(uint16_t*)&hy;
    uint32_t r;
    asm("mov.b32 %0, {%1, %2};" : "=r"(r) : "h"(ux), "h"(uy));
    return r;
}

// ============================================================
// bf16x2 3-pass GEMM, TMA loads + ldmatrix fragment loads.
// D = sum_k A[m,k]*B[n,k] (NT). Tile 256x128, BK=64, 512 thr, 2-stage.
// SMEM per stage: Ah(32K) Al(32K) Bh(16K) Bl(16K) = 96KB, TMA SW128.
// All tile rows are 128 bytes; swizzled 16B-unit index = u ^ (row&7),
// and row&7 == lane&7 for every ldmatrix row -> uniform address math.
// MODE 0: proj Q/K  (+bias, bf16 hi/lo split row-major store)
// MODE 1: proj V    (+bias, tf32-rounded fp32 TRANSPOSED store -> Vt)
// MODE 2: scores    (triangle grid, fp32 store to S)
// ============================================================
#define BSTG 98304
#define BSMEM_BYTES (2*BSTG)

template<int MODE>
__global__ void __launch_bounds__(512, 1) gemm_bf16(
    const __grid_constant__ CUtensorMap mAh, const __grid_constant__ CUtensorMap mAl,
    const __grid_constant__ CUtensorMap mBh, const __grid_constant__ CUtensorMap mBl,
    float* __restrict__ outf, bf16* __restrict__ oh, bf16* __restrict__ ol,
    const float* __restrict__ bias)
{
    const int m0 = blockIdx.y * 256, n0 = blockIdx.x * 128;
    if (MODE == 2 && n0 >= m0 + 256) return;

    extern __shared__ __align__(1024) char smem[];
    __shared__ __align__(8) uint64_t mbar[2];
    const uint32_t sb = smem_u32(smem);
    const uint32_t mb0 = smem_u32(&mbar[0]), mb1 = smem_u32(&mbar[1]);
    const int tid = threadIdx.x;
    const int lane = tid & 31, warp = tid >> 5;
    const int wm = warp >> 2, wn = warp & 3;
    const int g = lane >> 2, c = lane & 3;
    const int b = blockIdx.z;

    const int rowA = (MODE == 2) ? b*T + m0 : m0;
    const int rowB = (MODE == 2) ? b*T + n0 : n0;
    const int nch = E/64;  // 16

    if (tid == 0) { MBAR_INIT(mb0, 1); MBAR_INIT(mb1, 1); }
    __syncthreads();

    auto issue = [&](int ck) {
        uint32_t st = ck & 1;
        uint32_t base = sb + st*BSTG;
        uint32_t mb = st ? mb1 : mb0;
        MBAR_EXPECT(mb, BSTG);
        tma2d(base + 0,     &mAh, 64*ck, rowA, mb);
        tma2d(base + 32768, &mAl, 64*ck, rowA, mb);
        tma2d(base + 65536, &mBh, 64*ck, rowB, mb);
        tma2d(base + 81920, &mBl, 64*ck, rowB, mb);
    };
    if (tid == 0) { issue(0); issue(1); }

    float acc[4][4][4];
    #pragma unroll
    for (int mi = 0; mi < 4; mi++)
        #pragma unroll
        for (int ni = 0; ni < 4; ni++)
            #pragma unroll
            for (int q = 0; q < 4; q++) acc[mi][ni][q] = 0.f;

    // ldmatrix per-lane addressing
    const int lmat = lane >> 3, lrow = lane & 7;
    const int aBit = lmat >> 1, bBit = lmat & 1;
    uint32_t aRow[4], bRow[2];
    #pragma unroll
    for (int mi = 0; mi < 4; mi++)
        aRow[mi] = (uint32_t)((wm*64 + mi*16 + ((lmat & 1) << 3) + lrow) * 128);
    #pragma unroll
    for (int p = 0; p < 2; p++)
        bRow[p] = (uint32_t)((wn*32 + p*16 + ((lmat >> 1) << 3) + lrow) * 128);

    for (int ck = 0; ck < nch; ck++) {
        MBAR_WAIT((ck & 1) ? mb1 : mb0, (ck >> 1) & 1);

        const uint32_t stb = sb + (ck & 1)*BSTG;
        const uint32_t Ah = stb, Al = stb + 32768, Bh = stb + 65536, Bl = stb + 81920;

        #pragma unroll
        for (int ks = 0; ks < 4; ks++) {
            const uint32_t aU = (uint32_t)(((2*ks + aBit) ^ lrow) << 4);
            const uint32_t bU = (uint32_t)(((2*ks + bBit) ^ lrow) << 4);
            uint32_t bh[4][2], bl[4][2];
            ldsm4(bh[0][0], bh[0][1], bh[1][0], bh[1][1], Bh + bRow[0] + bU);
            ldsm4(bh[2][0], bh[2][1], bh[3][0], bh[3][1], Bh + bRow[1] + bU);
            ldsm4(bl[0][0], bl[0][1], bl[1][0], bl[1][1], Bl + bRow[0] + bU);
            ldsm4(bl[2][0], bl[2][1], bl[3][0], bl[3][1], Bl + bRow[1] + bU);
            uint32_t af[4][4];
            #pragma unroll
            for (int mi = 0; mi < 4; mi++)
                ldsm4(af[mi][0], af[mi][1], af[mi][2], af[mi][3], Ah + aRow[mi] + aU);
            // pass 1: Ah*Bh
            #pragma unroll
            for (int mi = 0; mi < 4; mi++)
                #pragma unroll
                for (int ni = 0; ni < 4; ni++)
                    mma16(acc[mi][ni], af[mi][0], af[mi][1], af[mi][2], af[mi][3],
                          bh[ni][0], bh[ni][1]);
            // pass 2: Ah*Bl
            #pragma unroll
            for (int mi = 0; mi < 4; mi++)
                #pragma unroll
                for (int ni = 0; ni < 4; ni++)
                    mma16(acc[mi][ni], af[mi][0], af[mi][1], af[mi][2], af[mi][3],
                          bl[ni][0], bl[ni][1]);
            // pass 3: Al*Bh
            #pragma unroll
            for (int mi = 0; mi < 4; mi++)
                ldsm4(af[mi][0], af[mi][1], af[mi][2], af[mi][3], Al + aRow[mi] + aU);
            #pragma unroll
            for (int mi = 0; mi < 4; mi++)
                #pragma unroll
                for (int ni = 0; ni < 4; ni++)
                    mma16(acc[mi][ni], af[mi][0], af[mi][1], af[mi][2], af[mi][3],
                          bh[ni][0], bh[ni][1]);
        }
        __syncthreads();
        if (tid == 0 && ck + 2 < nch) issue(ck + 2);
    }

    #pragma unroll
    for (int mi = 0; mi < 4; mi++) {
        #pragma unroll
        for (int ni = 0; ni < 4; ni++) {
            const int r1 = m0 + wm*64 + mi*16 + g, r2 = r1 + 8;
            const int col = n0 + wn*32 + ni*8 + 2*c;
            float* a = acc[mi][ni];
            if (MODE == 0) {
                float2 bs = *(const float2*)(bias + col);
                float y0 = a[0] + bs.x, y1 = a[1] + bs.y;
                float y2 = a[2] + bs.x, y3 = a[3] + bs.y;
                float h0 = __bfloat162float(__float2bfloat16(y0));
                float h1 = __bfloat162float(__float2bfloat16(y1));
                float h2 = __bfloat162float(__float2bfloat16(y2));
                float h3 = __bfloat162float(__float2bfloat16(y3));
                *(uint32_t*)(oh + (size_t)r1*E + col) = pack_bf2(y0, y1);
                *(uint32_t*)(ol + (size_t)r1*E + col) = pack_bf2(y0 - h0, y1 - h1);
                *(uint32_t*)(oh + (size_t)r2*E + col) = pack_bf2(y2, y3);
                *(uint32_t*)(ol + (size_t)r2*E + col) = pack_bf2(y2 - h2, y3 - h3);
            } else if (MODE == 1) {
                float2 bs = *(const float2*)(bias + col);
                const size_t bo = (size_t)(m0 / T) * E * T;
                const int tl1 = (m0 % T) + wm*64 + mi*16 + g, tl2 = tl1 + 8;
                outf[bo + (size_t)col*T     + tl1] = tf32_rna(a[0] + bs.x);
                outf[bo + (size_t)(col+1)*T + tl1] = tf32_rna(a[1] + bs.y);
                outf[bo + (size_t)col*T     + tl2] = tf32_rna(a[2] + bs.x);
                outf[bo + (size_t)(col+1)*T + tl2] = tf32_rna(a[3] + bs.y);
            } else {
                float* Sb = outf + (size_t)b*T*T;
                *(float2*)(Sb + (size_t)r1*T + col) = make_float2(a[0], a[1]);
                *(float2*)(Sb + (size_t)r2*T + col) = make_float2(a[2], a[3]);
            }
        }
    }
}

// ============================================================
// out GEMM, TMA + ldmatrix: O = P @ Vt^T, tf32 1-pass, 256x128, BK=32, 2-stage
// fp32 rows = 128B; ldmatrix.b16 loads 8x(16B) rows — typeless, works for tf32.
// ============================================================
#define OSTG 49152
#define OSMEM_BYTES (2*OSTG)

__global__ void __launch_bounds__(512, 1) gemm_out(
    const __grid_constant__ CUtensorMap mA, const __grid_constant__ CUtensorMap mB,
    float* __restrict__ out0)
{
    const int m0 = blockIdx.y * 256, n0 = blockIdx.x * 128;
    extern __shared__ __align__(1024) char smem[];
    __shared__ __align__(8) uint64_t mbar[2];
    const uint32_t sb = smem_u32(smem);
    const uint32_t mb0 = smem_u32(&mbar[0]), mb1 = smem_u32(&mbar[1]);
    const int tid = threadIdx.x;
    const int lane = tid & 31, warp = tid >> 5;
    const int wm = warp >> 2, wn = warp & 3;
    const int g = lane >> 2, c = lane & 3;
    const int b = blockIdx.z;

    const int rowA = b*T + m0;
    const int rowB = b*E + n0;
    const int nch = m0/32 + 8;

    if (tid == 0) { MBAR_INIT(mb0, 1); MBAR_INIT(mb1, 1); }
    __syncthreads();

    auto issue = [&](int ck) {
        uint32_t st = ck & 1;
        uint32_t base = sb + st*OSTG;
        uint32_t mb = st ? mb1 : mb0;
        MBAR_EXPECT(mb, OSTG);
        tma2d(base + 0,     &mA, 32*ck, rowA, mb);
        tma2d(base + 32768, &mB, 32*ck, rowB, mb);
    };
    if (tid == 0) { issue(0); issue(1); }

    float acc[4][4][4];
    #pragma unroll
    for (int mi = 0; mi < 4; mi++)
        #pragma unroll
        for (int ni = 0; ni < 4; ni++)
            #pragma unroll
            for (int q = 0; q < 4; q++) acc[mi][ni][q] = 0.f;

    const int lmat = lane >> 3, lrow = lane & 7;
    const int aBit = lmat >> 1, bBit = lmat & 1;
    uint32_t aRow[4], bRow[2];
    #pragma unroll
    for (int mi = 0; mi < 4; mi++)
        aRow[mi] = (uint32_t)((wm*64 + mi*16 + ((lmat & 1) << 3) + lrow) * 128);
    #pragma unroll
    for (int p = 0; p < 2; p++)
        bRow[p] = (uint32_t)((wn*32 + p*16 + ((lmat >> 1) << 3) + lrow) * 128);

    for (int ck = 0; ck < nch; ck++) {
        MBAR_WAIT((ck & 1) ? mb1 : mb0, (ck >> 1) & 1);

        const uint32_t stb = sb + (ck & 1)*OSTG;
        const uint32_t Aa = stb, Bb = stb + 32768;

        #pragma unroll
        for (int ks = 0; ks < 4; ks++) {
            const uint32_t aU = (uint32_t)(((2*ks + aBit) ^ lrow) << 4);
            const uint32_t bU = (uint32_t)(((2*ks + bBit) ^ lrow) << 4);
            uint32_t bh[4][2];
            ldsm4(bh[0][0], bh[0][1], bh[1][0], bh[1][1], Bb + bRow[0] + bU);
            ldsm4(bh[2][0], bh[2][1], bh[3][0], bh[3][1], Bb + bRow[1] + bU);
            #pragma unroll
            for (int mi = 0; mi < 4; mi++) {
                uint32_t a0, a1, a2, a3;
                ldsm4(a0, a1, a2, a3, Aa + aRow[mi] + aU);
                #pragma unroll
                for (int ni = 0; ni < 4; ni++)
                    mma8(acc[mi][ni], a0, a1, a2, a3, bh[ni][0], bh[ni][1]);
            }
        }
        __syncthreads();
        if (tid == 0 && ck + 2 < nch) issue(ck + 2);
    }

    #pragma unroll
    for (int mi = 0; mi < 4; mi++) {
        #pragma unroll
        for (int ni = 0; ni < 4; ni++) {
            const int r1 = m0 + wm*64 + mi*16 + g, r2 = r1 + 8;
            const int col = n0 + wn*32 + ni*8 + 2*c;
            float* a = acc[mi][ni];
            float* Ob = out0 + (size_t)b*T*E;
            *(float2*)(Ob + (size_t)r1*E + col) = make_float2(a[0], a[1]);
            *(float2*)(Ob + (size_t)r2*E + col) = make_float2(a[2], a[3]);
        }
    }
}

// ------------------------- elementwise kernels -------------------------
__global__ void __launch_bounds__(256) splitk_bf(
    const float* __restrict__ src, bf16* __restrict__ dh, bf16* __restrict__ dl, int n4)
{
    int i = blockIdx.x * 256 + threadIdx.x;
    if (i >= n4) return;
    float4 v = ((const float4*)src)[i];
    uint32_t h0 = pack_bf2(v.x, v.y), h1 = pack_bf2(v.z, v.w);
    float r0 = v.x - __bfloat162float(__float2bfloat16(v.x));
    float r1 = v.y - __bfloat162float(__float2bfloat16(v.y));
    float r2 = v.z - __bfloat162float(__float2bfloat16(v.z));
    float r3 = v.w - __bfloat162float(__float2bfloat16(v.w));
    uint32_t l0 = pack_bf2(r0, r1), l1 = pack_bf2(r2, r3);
    ((uint2*)dh)[i] = make_uint2(h0, h1);
    ((uint2*)dl)[i] = make_uint2(l0, l1);
}

// per-key-column j stats over i>=j (softmax over QUERY axis quirk).
// 4 independent accumulator strips per thread -> MLP=4, 4x fewer serial iters.
__global__ void __launch_bounds__(256) colstats()
{
    const int bb = blockIdx.y;
    const int j0 = blockIdx.x * 32;
    const int c = threadIdx.x & 31, r = threadIdx.x >> 5;
    const int j = j0 + c;
    const float* S = g_S + (size_t)bb*T*T;
    float m0v = -INFINITY, m1v = -INFINITY, m2v = -INFINITY, m3v = -INFINITY;
    float l0v = 0.f, l1v = 0.f, l2v = 0.f, l3v = 0.f;
    #define UPD(MM, LL, II) do { int _i = (II); if (_i >= j) { \
        float v = S[(size_t)_i*T + j]; \
        if (v <= MM) LL += __expf(v - MM); \
        else { LL = LL * __expf(MM - v) + 1.f; MM = v; } } } while(0)
    for (int i = j0 + r; i < T; i += 32) {
        UPD(m0v, l0v, i);
        UPD(m1v, l1v, i + 8);
        UPD(m2v, l2v, i + 16);
        UPD(m3v, l3v, i + 24);
    }
    #undef UPD
    // merge 4 strips
    float M = m0v, L = l0v;
    #define MRG(MM, LL) do { \
        if (MM > M) { L = L * __expf(M - MM) + LL; M = MM; } \
        else if (LL > 0.f) L += LL * __expf(MM - M); } while(0)
    MRG(m1v, l1v); MRG(m2v, l2v); MRG(m3v, l3v);
    __shared__ float sm_[8][33], sl_[8][33];
    sm_[r][c] = M; sl_[r][c] = L;
    __syncthreads();
    if (r == 0) {
        #pragma unroll
        for (int rr = 1; rr < 8; rr++) {
            float mm = sm_[rr][c], ll = sl_[rr][c];
            MRG(mm, ll);
        }
        g_M [bb*T + j] = M;
        g_Li[bb*T + j] = 1.f / L;
    }
    #undef MRG
}

__global__ void __launch_bounds__(256) psplit()
{
    const int jt = blockIdx.x, it = blockIdx.y;
    const int bb = blockIdx.z;
    const size_t base = (size_t)bb*T*T;
    const int i0 = it*128, j0 = jt*128;
    if (jt > it) {
        if (jt == it + 1 && (it & 1) == 0) {
            for (int idx = threadIdx.x; idx < 128*32; idx += 256) {
                int rr = idx >> 5, c4 = idx & 31;
                *(float4*)(g_Ph + base + (size_t)(i0+rr)*T + j0 + c4*4) =
                    make_float4(0.f, 0.f, 0.f, 0.f);
            }
        }
        return;
    }
    for (int idx = threadIdx.x; idx < 128*32; idx += 256) {
        int rr = idx >> 5, c4 = idx & 31;
        int i = i0 + rr, j = j0 + c4*4;
        float4 s = *(const float4*)(g_S + base + (size_t)i*T + j);
        float sv[4] = {s.x, s.y, s.z, s.w};
        float h[4];
        #pragma unroll
        for (int q = 0; q < 4; q++) {
            int jj = j + q;
            float p = (jj <= i) ? __expf(sv[q] - g_M[bb*T + jj]) * g_Li[bb*T + jj] : 0.f;
            h[q] = tf32_rna(p);
        }
        *(float4*)(g_Ph + base + (size_t)i*T + j) = make_float4(h[0], h[1], h[2], h[3]);
    }
}

// ------------------------- host -------------------------
typedef CUresult (*PFN_encode)(CUtensorMap*, CUtensorMapDataType, cuuint32_t, void*,
    const cuuint64_t*, const cuuint64_t*, const cuuint32_t*, const cuuint32_t*,
    CUtensorMapInterleave, CUtensorMapSwizzle, CUtensorMapL2promotion, CUtensorMapFloatOOBfill);

static void mk2d(PFN_encode enc, CUtensorMap* tm, void* p, CUtensorMapDataType dt,
                 uint64_t w, uint64_t h, uint32_t bw, uint32_t bh, uint32_t esize) {
    cuuint64_t dims[2]    = {w, h};
    cuuint64_t strides[1] = {w * esize};
    cuuint32_t box[2]     = {bw, bh};
    cuuint32_t es[2]      = {1, 1};
    enc(tm, dt, 2, p, dims, strides, box, es,
        CU_TENSOR_MAP_INTERLEAVE_NONE, CU_TENSOR_MAP_SWIZZLE_128B,
        CU_TENSOR_MAP_L2_PROMOTION_L2_128B, CU_TENSOR_MAP_FLOAT_OOB_FILL_NONE);
}

extern "C" void kernel_launch(void* const* d_in, const int* in_sizes, int n_in,
                              void* d_out, int out_size)
{
    const float* x_emb = (const float*)d_in[0];
    const float* Wk = (const float*)d_in[2];
    const float* bk = (const float*)d_in[3];
    const float* Wq = (const float*)d_in[4];
    const float* bq = (const float*)d_in[5];
    const float* Wv = (const float*)d_in[6];
    const float* bv = (const float*)d_in[7];
    float* out = (float*)d_out;

    void* fp = nullptr;
    cudaDriverEntryPointQueryResult qst;
    cudaGetDriverEntryPointByVersion("cuTensorMapEncodeTiled", &fp, 12000, cudaEnableDefault, &qst);
    PFN_encode enc = (PFN_encode)fp;

    void *Xbh,*Xbl,*Wqh,*Wql,*Wkh,*Wkl,*Wvh,*Wvl,*Qbh,*Qbl,*Kbh,*Kbl,*Vth,*Sp,*Ph;
    cudaGetSymbolAddress(&Xbh, g_Xbh); cudaGetSymbolAddress(&Xbl, g_Xbl);
    cudaGetSymbolAddress(&Wqh, g_Wqh); cudaGetSymbolAddress(&Wql, g_Wql);
    cudaGetSymbolAddress(&Wkh, g_Wkh); cudaGetSymbolAddress(&Wkl, g_Wkl);
    cudaGetSymbolAddress(&Wvh, g_Wvh); cudaGetSymbolAddress(&Wvl, g_Wvl);
    cudaGetSymbolAddress(&Qbh, g_Qbh); cudaGetSymbolAddress(&Qbl, g_Qbl);
    cudaGetSymbolAddress(&Kbh, g_Kbh); cudaGetSymbolAddress(&Kbl, g_Kbl);
    cudaGetSymbolAddress(&Vth, g_Vth);
    cudaGetSymbolAddress(&Sp, g_S);    cudaGetSymbolAddress(&Ph, g_Ph);

    const CUtensorMapDataType BF = CU_TENSOR_MAP_DATA_TYPE_BFLOAT16;
    const CUtensorMapDataType F32 = CU_TENSOR_MAP_DATA_TYPE_FLOAT32;
    CUtensorMap tXh, tXl, tWqh, tWql, tWkh, tWkl, tWvh, tWvl;
    CUtensorMap tQh, tQl, tKh, tKl, tP, tV;
    mk2d(enc, &tXh, Xbh, BF, E, MT, 64, 256, 2);
    mk2d(enc, &tXl, Xbl, BF, E, MT, 64, 256, 2);
    mk2d(enc, &tWqh, Wqh, BF, E, E, 64, 128, 2);
    mk2d(enc, &tWql, Wql, BF, E, E, 64, 128, 2);
    mk2d(enc, &tWkh, Wkh, BF, E, E, 64, 128, 2);
    mk2d(enc, &tWkl, Wkl, BF, E, E, 64, 128, 2);
    mk2d(enc, &tWvh, Wvh, BF, E, E, 64, 128, 2);
    mk2d(enc, &tWvl, Wvl, BF, E, E, 64, 128, 2);
    mk2d(enc, &tQh, Qbh, BF, E, MT, 64, 256, 2);
    mk2d(enc, &tQl, Qbl, BF, E, MT, 64, 256, 2);
    mk2d(enc, &tKh, Kbh, BF, E, MT, 64, 128, 2);
    mk2d(enc, &tKl, Kbl, BF, E, MT, 64, 128, 2);
    mk2d(enc, &tP, Ph, F32, T, (uint64_t)NB*T, 32, 256, 4);
    mk2d(enc, &tV, Vth, F32, T, (uint64_t)NB*E, 32, 128, 4);

    cudaFuncSetAttribute(gemm_bf16<0>, cudaFuncAttributeMaxDynamicSharedMemorySize, BSMEM_BYTES);
    cudaFuncSetAttribute(gemm_bf16<1>, cudaFuncAttributeMaxDynamicSharedMemorySize, BSMEM_BYTES);
    cudaFuncSetAttribute(gemm_bf16<2>, cudaFuncAttributeMaxDynamicSharedMemorySize, BSMEM_BYTES);
    cudaFuncSetAttribute(gemm_out,     cudaFuncAttributeMaxDynamicSharedMemorySize, OSMEM_BYTES);

    splitk_bf<<<(MT*E/4 + 255)/256, 256>>>(x_emb, (bf16*)Xbh, (bf16*)Xbl, MT*E/4);
    splitk_bf<<<(E*E/4 + 255)/256, 256>>>(Wq, (bf16*)Wqh, (bf16*)Wql, E*E/4);
    splitk_bf<<<(E*E/4 + 255)/256, 256>>>(Wk, (bf16*)Wkh, (bf16*)Wkl, E*E/4);
    splitk_bf<<<(E*E/4 + 255)/256, 256>>>(Wv, (bf16*)Wvh, (bf16*)Wvl, E*E/4);

    dim3 gp(E/128, MT/256);
    gemm_bf16<0><<<gp, 512, BSMEM_BYTES>>>(tXh, tXl, tWqh, tWql,
                                           nullptr, (bf16*)Qbh, (bf16*)Qbl, bq);
    gemm_bf16<0><<<gp, 512, BSMEM_BYTES>>>(tXh, tXl, tWkh, tWkl,
                                           nullptr, (bf16*)Kbh, (bf16*)Kbl, bk);
    gemm_bf16<1><<<gp, 512, BSMEM_BYTES>>>(tXh, tXl, tWvh, tWvl,
                                           (float*)Vth, nullptr, nullptr, bv);

    dim3 gs(T/128, T/256, NB);
    gemm_bf16<2><<<gs, 512, BSMEM_BYTES>>>(tQh, tQl, tKh, tKl,
                                           (float*)Sp, nullptr, nullptr, nullptr);

    dim3 gc(T/32, NB);
    colstats<<<gc, 256>>>();
    psplit<<<dim3(T/128, T/128, NB), 256>>>();

    dim3 go(E/128, T/256, NB);
    gemm_out<<<go, 512, OSMEM_BYTES>>>(tP, tV, out);
}